// round 1
// baseline (speedup 1.0000x reference)
#include <cuda_runtime.h>

#define N_NODES 200000
#define D_IN    256
#define D_OUT   256
#define BATCH   4096
#define K1      25
#define K2      10
#define M_L1    (BATCH * (1 + K2))   // 45056

// ---------------- scratch (no allocations allowed) ----------------
__device__ float g_X1[(size_t)M_L1 * 2 * D_IN];   // [45056, 512]  ~92 MB
__device__ float g_h1[(size_t)M_L1 * D_OUT];      // [45056, 256]  ~46 MB
__device__ float g_X2[(size_t)BATCH * 2 * D_OUT]; // [4096, 512]   ~8 MB
__device__ int   g_is64;                          // index dtype flag

// ---------------- index dtype probe ----------------
// If the harness passes int64, values read as int64 are all in [0, N_NODES).
// If it passes int32, an int64 read merges two int32s -> almost surely huge.
__global__ void detect_idx_dtype(const void* __restrict__ nb) {
    const long long* p = (const long long*)nb;
    int ok64 = 1;
    #pragma unroll
    for (int i = 0; i < 64; i++) {
        long long v = p[i];
        if (v < 0 || v >= (long long)N_NODES) ok64 = 0;
    }
    g_is64 = ok64;
}

__device__ __forceinline__ int get_idx(const void* __restrict__ p, int i) {
    if (g_is64) return (int)((const long long*)p)[i];
    return ((const int*)p)[i];
}

// ---------------- layer-1 gather + mean ----------------
// block = one l1 row (256 threads, one per feature dim)
__global__ void gather1_kernel(const float* __restrict__ features,
                               const void* __restrict__ nodes_batch,
                               const void* __restrict__ neigh2,
                               const void* __restrict__ neigh1) {
    int m = blockIdx.x;
    int t = threadIdx.x;  // 0..255
    __shared__ int idx[K1 + 1];
    if (t < K1) idx[t + 1] = get_idx(neigh1, m * K1 + t);
    if (t == K1) idx[0] = (m < BATCH) ? get_idx(nodes_batch, m)
                                      : get_idx(neigh2, m - BATCH);
    __syncthreads();

    float selfv = features[(size_t)idx[0] * D_IN + t];
    float acc = 0.f;
    #pragma unroll
    for (int k = 0; k < K1; k++)
        acc += features[(size_t)idx[k + 1] * D_IN + t];

    size_t base = (size_t)m * (2 * D_IN);
    g_X1[base + t]        = selfv;
    g_X1[base + D_IN + t] = acc * (1.0f / K1);
}

// ---------------- layer-2 concat build ----------------
__global__ void build_x2_kernel() {
    int b = blockIdx.x;    // 0..4095
    int t = threadIdx.x;   // 0..255
    float selfv = g_h1[(size_t)b * D_OUT + t];
    float acc = 0.f;
    #pragma unroll
    for (int j = 0; j < K2; j++)
        acc += g_h1[(size_t)(BATCH + b * K2 + j) * D_OUT + t];
    size_t base = (size_t)b * (2 * D_OUT);
    g_X2[base + t]         = selfv;
    g_X2[base + D_OUT + t] = acc * (1.0f / K2);
}

// ---------------- fp32 tiled GEMM: C = relu_opt(A @ W^T) ----------------
// A: [Mrows, Kdim] row-major, W: [Ncols, Kdim] row-major (so both K-contig)
// BM=BN=64, BK=16, 256 threads, 4x4 micro-tile per thread.
template <bool RELU>
__global__ void sgemm_relu_kernel(const float* __restrict__ A,
                                  const float* __restrict__ W,
                                  float* __restrict__ C,
                                  int Mrows, int Kdim, int Ncols) {
    __shared__ float As[16][64];
    __shared__ float Ws[16][64];

    int tid = threadIdx.x;
    int tx = tid & 15;        // 0..15  (n direction)
    int ty = tid >> 4;        // 0..15  (m direction)
    int bm = blockIdx.x * 64;
    int bn = blockIdx.y * 64;

    int lr = tid >> 2;         // 0..63 : row within tile for loads
    int lk = (tid & 3) * 4;    // 0,4,8,12 : k offset for float4 load

    const float* Aptr = A + (size_t)(bm + lr) * Kdim + lk;
    const float* Wptr = W + (size_t)(bn + lr) * Kdim + lk;

    float acc[4][4];
    #pragma unroll
    for (int i = 0; i < 4; i++)
        #pragma unroll
        for (int j = 0; j < 4; j++) acc[i][j] = 0.f;

    for (int k0 = 0; k0 < Kdim; k0 += 16) {
        float4 a4 = *(const float4*)(Aptr + k0);
        float4 w4 = *(const float4*)(Wptr + k0);
        As[lk + 0][lr] = a4.x; As[lk + 1][lr] = a4.y;
        As[lk + 2][lr] = a4.z; As[lk + 3][lr] = a4.w;
        Ws[lk + 0][lr] = w4.x; Ws[lk + 1][lr] = w4.y;
        Ws[lk + 2][lr] = w4.z; Ws[lk + 3][lr] = w4.w;
        __syncthreads();

        #pragma unroll
        for (int k = 0; k < 16; k++) {
            float4 ra = *(const float4*)&As[k][ty * 4];
            float4 rb = *(const float4*)&Ws[k][tx * 4];
            float av[4] = {ra.x, ra.y, ra.z, ra.w};
            float bv[4] = {rb.x, rb.y, rb.z, rb.w};
            #pragma unroll
            for (int i = 0; i < 4; i++)
                #pragma unroll
                for (int j = 0; j < 4; j++)
                    acc[i][j] = fmaf(av[i], bv[j], acc[i][j]);
        }
        __syncthreads();
    }

    #pragma unroll
    for (int i = 0; i < 4; i++) {
        int row = bm + ty * 4 + i;
        float4 out;
        float v0 = acc[i][0], v1 = acc[i][1], v2 = acc[i][2], v3 = acc[i][3];
        if (RELU) {
            v0 = fmaxf(v0, 0.f); v1 = fmaxf(v1, 0.f);
            v2 = fmaxf(v2, 0.f); v3 = fmaxf(v3, 0.f);
        }
        out.x = v0; out.y = v1; out.z = v2; out.w = v3;
        *(float4*)&C[(size_t)row * Ncols + bn + tx * 4] = out;
    }
}

// ---------------- launch ----------------
extern "C" void kernel_launch(void* const* d_in, const int* in_sizes, int n_in,
                              void* d_out, int out_size) {
    const float* features    = (const float*)d_in[0];
    const float* W1          = (const float*)d_in[1];
    const float* W2          = (const float*)d_in[2];
    const void*  nodes_batch = d_in[3];
    const void*  neigh2      = d_in[4];
    const void*  neigh1      = d_in[5];
    float* out = (float*)d_out;

    float *pX1, *pH1, *pX2;
    cudaGetSymbolAddress((void**)&pX1, g_X1);
    cudaGetSymbolAddress((void**)&pH1, g_h1);
    cudaGetSymbolAddress((void**)&pX2, g_X2);

    detect_idx_dtype<<<1, 1>>>(nodes_batch);
    gather1_kernel<<<M_L1, 256>>>(features, nodes_batch, neigh2, neigh1);

    // h1 = relu(X1 @ W1^T)  : [45056, 512] x [256, 512]^T -> [45056, 256]
    sgemm_relu_kernel<true><<<dim3(M_L1 / 64, D_OUT / 64), 256>>>(
        pX1, W1, pH1, M_L1, 2 * D_IN, D_OUT);

    build_x2_kernel<<<BATCH, 256>>>();

    // h2 = relu(X2 @ W2^T)  : [4096, 512] x [256, 512]^T -> [4096, 256]
    sgemm_relu_kernel<true><<<dim3(BATCH / 64, D_OUT / 64), 256>>>(
        pX2, W2, out, BATCH, 2 * D_OUT, D_OUT);
}